// round 13
// baseline (speedup 1.0000x reference)
#include <cuda_runtime.h>
#include <float.h>

// ROI max pool, TWO kernels:
//  A) prepare: register transpose [2,256,50,50] -> g_feat_t [2,50,50,256]
//     (coalesced loads, STG.128 scatter, no smem/sync) + prep branch that
//     precomputes per-(roi,bin) bounds into g_meta.
//  B) pool: 6272 blocks x 64 thr (proven shape), warp = bin x 128 channels,
//     width<=8 unrolled clamped loads (high MLP), stores DIRECTLY to
//     out[n][c][ij] (4 scalar stores/thread, fire-and-forget; overlaps the
//     load latency). No g_tmp, no reshape kernel.

#define OUTP 7
#define NBINS 49
#define CCH  256
#define HH   50
#define WW   50
#define HWSZ (HH * WW)
#define BB   2
#define CS   (CCH / 4)

#define TBLKS (79 * 8 * 2)     // transpose blocks: 1264
#define PBLKS 25               // prep blocks: ceil(6272/256)

__device__ __align__(16) float g_feat_t[BB * HWSZ * CCH];   // 5.12 MB
__device__ int4 g_meta[128 * NBINS];

// ---------------- A) prepare: transpose + prep fused ----------------
__global__ __launch_bounds__(256) void prepare_kernel(
    const float* __restrict__ feat, const float* __restrict__ rois)
{
    int bi = blockIdx.x;
    if (bi < TBLKS) {
        // transpose: bi -> (b, c-slab, hw-chunk)
        int b   = bi / (79 * 8);
        int rem = bi - b * (79 * 8);
        int cy  = rem / 79;            // 0..7  -> 32-ch slab
        int hx  = rem - cy * 79;       // 0..78 -> 32-hw chunk
        int c0   = cy * 32 + (threadIdx.x >> 5) * 4;
        int lane = threadIdx.x & 31;
        int hw   = hx * 32 + lane;
        if (hw < HWSZ) {
            const float* src = feat + ((size_t)b * CCH + c0) * HWSZ + hw;
            float4 o;
            o.x = __ldg(src);
            o.y = __ldg(src + HWSZ);
            o.z = __ldg(src + 2 * HWSZ);
            o.w = __ldg(src + 3 * HWSZ);
            *(float4*)(g_feat_t + ((size_t)b * HWSZ + hw) * CCH + c0) = o;
        }
    } else {
        // prep: per-(roi,bin) bounds
        int t = (bi - TBLKS) * 256 + threadIdx.x;
        if (t >= 128 * NBINS) return;
        int n  = t / NBINS;
        int ij = t - n * NBINS;
        int i  = ij / OUTP;
        int j  = ij - i * OUTP;

        const float* r = rois + n * 5;
        int im = (int)rintf(r[0]);
        int x1 = (int)rintf(r[1] * 0.0625f);
        int y1 = (int)rintf(r[2] * 0.0625f);
        int x2 = (int)rintf(r[3] * 0.0625f);
        int y2 = (int)rintf(r[4] * 0.0625f);
        unsigned h = (unsigned)(y2 - y1 + 1);
        unsigned w = (unsigned)(x2 - x1 + 1);

        int ys = (int)((unsigned)(i * h) / 7u) + y1;
        int ye = (int)(((unsigned)((i + 1) * h) + 6u) / 7u) + y1;
        int xs = (int)((unsigned)(j * w) / 7u) + x1;
        int xe = (int)(((unsigned)((j + 1) * w) + 6u) / 7u) + x1;
        ye = min(ye, HH);  xe = min(xe, WW);

        int4 m;
        m.x = im * HWSZ + ys * WW + xs;
        m.y = ye - ys;
        m.z = xe - xs - 1;
        m.w = 0;
        g_meta[t] = m;
    }
}

__device__ __forceinline__ float4 fmax4(float4 a, float4 b)
{
    return make_float4(fmaxf(a.x, b.x), fmaxf(a.y, b.y),
                       fmaxf(a.z, b.z), fmaxf(a.w, b.w));
}

// ---------------- B) pool: 6272 blocks x 64 threads, direct output ---------
__global__ __launch_bounds__(64) void roi_pool_kernel(float* __restrict__ out)
{
    int task = blockIdx.x;            // n*NBINS + ij
    int lane = threadIdx.x & 31;
    int cg   = threadIdx.x >> 5;

    int4 m = __ldg(&g_meta[task]);
    int wm1 = m.z;

    const float4* base = (const float4*)g_feat_t
                       + (size_t)m.x * CS + cg * 32 + lane;

    float4 acc = make_float4(-FLT_MAX, -FLT_MAX, -FLT_MAX, -FLT_MAX);
    for (int r = 0; r < m.y; ++r) {
        const float4* row = base + (size_t)r * (WW * CS);
        float4 v0 = __ldg(row);
        float4 v1 = __ldg(row + min(1, wm1) * CS);
        float4 v2 = __ldg(row + min(2, wm1) * CS);
        float4 v3 = __ldg(row + min(3, wm1) * CS);
        float4 m0 = fmax4(v0, v1);
        float4 m1 = fmax4(v2, v3);
        if (wm1 >= 4) {               // warp-uniform branch
            float4 v4 = __ldg(row + 4 * CS);
            float4 v5 = __ldg(row + min(5, wm1) * CS);
            float4 v6 = __ldg(row + min(6, wm1) * CS);
            float4 v7 = __ldg(row + min(7, wm1) * CS);
            m0 = fmax4(m0, fmax4(v4, v5));
            m1 = fmax4(m1, fmax4(v6, v7));
        }
        acc = fmax4(acc, fmax4(m0, m1));
    }

    // direct store: out[n][c][ij], c = cg*128 + lane*4 + {0..3}
    int n  = task / NBINS;
    int ij = task - n * NBINS;
    float* dst = out + ((size_t)n * CCH + cg * 128 + lane * 4) * NBINS + ij;
    dst[0 * NBINS] = acc.x;
    dst[1 * NBINS] = acc.y;
    dst[2 * NBINS] = acc.z;
    dst[3 * NBINS] = acc.w;
}

extern "C" void kernel_launch(void* const* d_in, const int* in_sizes, int n_in,
                              void* d_out, int out_size)
{
    const float* feat = (const float*)d_in[0];
    const float* rois = (const float*)d_in[1];
    float* out = (float*)d_out;

    prepare_kernel<<<TBLKS + PBLKS, 256>>>(feat, rois);

    roi_pool_kernel<<<128 * NBINS, 64>>>(out);
}